// round 14
// baseline (speedup 1.0000x reference)
#include <cuda_runtime.h>
#include <cuda_bf16.h>
#include <cstdint>

// Problem constants
#define BB 512
#define DD 128
#define CC 100000
#define TCB 128                    // proxies per tile in k_big
#define NTB ((CC + TCB - 1) / TCB) // 782 tiles (last zero-padded)
#define ATT_EPS 1e-5f
#define PN_A 1600                  // pnorm 32-row groups fused into att launch
#define PN_X (CC / 32 - PN_A)      // remaining groups fused into xw launch

// Scratch (device globals; no allocations allowed)
__device__ float g_Xn[BB * DD];
__device__ float g_Pb[BB * DD];
__device__ float g_diag[BB];
__device__ float g_att[BB * BB];
__device__ float g_rowsum[BB];
__device__ float g_Dt[BB];
__device__ float g_Z[BB];
__device__ __align__(16) __nv_bfloat16 g_Xs16[BB * DD];
__device__ __align__(16) __nv_bfloat16 g_pn16[CC * DD];   // 3 * l2norm(proxies), bf16

// ---------------------------------------------------------------------------
// helpers
// ---------------------------------------------------------------------------
__device__ __forceinline__ uint32_t s2u(const void* p) {
    uint32_t a;
    asm("{ .reg .u64 t; cvta.to.shared.u64 t, %1; cvt.u32.u64 %0, t; }"
        : "=r"(a) : "l"(p));
    return a;
}

__device__ __forceinline__ float bred128(float v, float* s4) {
#pragma unroll
    for (int o = 16; o; o >>= 1) v += __shfl_xor_sync(0xffffffffu, v, o);
    __syncthreads();
    if ((threadIdx.x & 31) == 0) s4[threadIdx.x >> 5] = v;
    __syncthreads();
    return s4[0] + s4[1] + s4[2] + s4[3];
}

__device__ __forceinline__ void mma_bf16(float* acc, uint32_t a0, uint32_t a1,
                                         uint32_t a2, uint32_t a3,
                                         uint32_t b0, uint32_t b1) {
    asm volatile(
        "mma.sync.aligned.m16n8k16.row.col.f32.bf16.bf16.f32 "
        "{%0,%1,%2,%3}, {%4,%5,%6,%7}, {%8,%9}, {%0,%1,%2,%3};\n"
        : "+f"(acc[0]), "+f"(acc[1]), "+f"(acc[2]), "+f"(acc[3])
        : "r"(a0), "r"(a1), "r"(a2), "r"(a3), "r"(b0), "r"(b1));
}

__device__ __forceinline__ void ldsm4(uint32_t addr, uint32_t* r) {
    asm volatile("ldmatrix.sync.aligned.m8n8.x4.shared.b16 {%0,%1,%2,%3}, [%4];"
                 : "=r"(r[0]), "=r"(r[1]), "=r"(r[2]), "=r"(r[3]) : "r"(addr));
}

__device__ __forceinline__ uint32_t f2b2(float a, float b) {
    __nv_bfloat162 h = __floats2bfloat162_rn(a, b);
    return *(uint32_t*)&h;
}

// Bit-trick 2^y for y in [-60, 0] (quantized to 1/512, Schraudolph with
// mean-zero correction). No MUFU, no CVT: fma + IMAD + reinterpret.
//   t = y*512 + 1.5*2^23 -> mantissa holds 2^22 + round(y*512)
//   i = bits(t)*2^14 + BIAS  == round(y*2^23) + (127<<23) - CORR (mod 2^32)
#define EXP2_MAGIC 12582912.f
#define EXP2_BIAS 1064880098     // (127<<23) - round(0.0564*2^23)
__device__ __forceinline__ float exp2_fast(float y) {
    float t = fmaf(y, 512.f, EXP2_MAGIC);
    int i = (int)(__float_as_uint(t) * 16384u + (uint32_t)EXP2_BIAS);
    return __int_as_float(i);
}

// Robust class-id fetch (JAX x64-disabled materializes int32 for declared int64)
__device__ __forceinline__ int fetch_T(const int* T32, int b, int is64) {
    int t = is64 ? T32[2 * b] : T32[b];
    return min(max(t, 0), CC - 1);
}
__device__ __forceinline__ int detect_i64_block(const int* T32) {
    int ok = 1;
    for (int i = threadIdx.x; i < BB; i += blockDim.x)
        if (T32[2 * i + 1] != 0) ok = 0;
    return __syncthreads_and(ok);
}

// ---------------------------------------------------------------------------
// pnorm body: one 32-row group of g_pn16 = bf16(3*l2norm(proxy)), 256 threads,
// 8 threads per row. No smem, no barriers (safe to fuse into any launch).
// ---------------------------------------------------------------------------
__device__ __forceinline__ void pnorm_group(const float* __restrict__ proxies,
                                            int grp) {
    int tid = threadIdx.x;
    int r = grp * 32 + (tid >> 3);
    int sub = tid & 7;
    const float4* src = (const float4*)(proxies + (size_t)r * DD) + sub * 4;
    float4 q0 = src[0], q1 = src[1], q2 = src[2], q3 = src[3];
    float s = q0.x * q0.x + q0.y * q0.y + q0.z * q0.z + q0.w * q0.w
            + q1.x * q1.x + q1.y * q1.y + q1.z * q1.z + q1.w * q1.w
            + q2.x * q2.x + q2.y * q2.y + q2.z * q2.z + q2.w * q2.w
            + q3.x * q3.x + q3.y * q3.y + q3.z * q3.z + q3.w * q3.w;
    s += __shfl_xor_sync(0xffffffffu, s, 4);
    s += __shfl_xor_sync(0xffffffffu, s, 2);
    s += __shfl_xor_sync(0xffffffffu, s, 1);
    float sc = (s > 0.f) ? 3.f * rsqrtf(s) : 0.f;
    uint4 o0, o1;
    o0.x = f2b2(q0.x * sc, q0.y * sc); o0.y = f2b2(q0.z * sc, q0.w * sc);
    o0.z = f2b2(q1.x * sc, q1.y * sc); o0.w = f2b2(q1.z * sc, q1.w * sc);
    o1.x = f2b2(q2.x * sc, q2.y * sc); o1.y = f2b2(q2.z * sc, q2.w * sc);
    o1.z = f2b2(q3.x * sc, q3.y * sc); o1.w = f2b2(q3.z * sc, q3.w * sc);
    uint4* dst = (uint4*)(g_pn16 + (size_t)r * DD) + sub * 2;
    dst[0] = o0; dst[1] = o1;
}

// ---------------------------------------------------------------------------
// K1: Xn = l2norm(X); Pb = l2norm(proxies[T]); diag = <Pb,Xn>; zero Z/rowsum
// ---------------------------------------------------------------------------
__global__ void k_prep(const float* __restrict__ X,
                       const int* __restrict__ T32,
                       const float* __restrict__ proxies) {
    __shared__ float s4[4];
    int b = blockIdx.x, d = threadIdx.x;
    int is64 = detect_i64_block(T32);

    float x = X[b * DD + d];
    float s = bred128(x * x, s4);
    float xn = x / fmaxf(sqrtf(s), 1e-12f);
    g_Xn[b * DD + d] = xn;

    int t = fetch_T(T32, b, is64);
    float p = proxies[(size_t)t * DD + d];
    float s2 = bred128(p * p, s4);
    float pb = p / fmaxf(sqrtf(s2), 1e-12f);
    g_Pb[b * DD + d] = pb;

    float dg = bred128(pb * xn, s4);
    if (d == 0) g_diag[b] = dg;
    if (b < 4) { g_rowsum[b * DD + d] = 0.f; }
    if (d == 0) g_Z[b] = 0.f;
}

// ---------------------------------------------------------------------------
// K2 (fused): blocks [0,256): att tiles; blocks [256, 256+PN_A): pnorm groups.
// ---------------------------------------------------------------------------
#define SMEM_ATT ((3 * 32 * 129 + 32 + 32) * 4)
__global__ void __launch_bounds__(256) k_att_pn(const float* __restrict__ proxies) {
    int bid = blockIdx.x;
    if (bid >= 256) { pnorm_group(proxies, bid - 256); return; }

    extern __shared__ float smf[];
    float* PbS = smf;
    float* XnA = smf + 32 * 129;
    float* XnB = smf + 2 * 32 * 129;
    float* dgS = smf + 3 * 32 * 129;
    float* rsum = smf + 3 * 32 * 129 + 32;

    int tid = threadIdx.x;
    int b0 = (bid >> 4) * 32, j0 = (bid & 15) * 32;
    for (int i = tid; i < 32 * DD; i += 256) {
        int r = i >> 7, d = i & 127;
        PbS[r * 129 + d] = g_Pb[(b0 + r) * DD + d];
        XnA[r * 129 + d] = g_Xn[(b0 + r) * DD + d];
        XnB[r * 129 + d] = g_Xn[(j0 + r) * DD + d];
    }
    if (tid < 32) { dgS[tid] = g_diag[j0 + tid]; rsum[tid] = 0.f; }
    __syncthreads();

    int tx = (tid & 15) * 2, ty = (tid >> 4) * 2;
    float apb00 = 0, apb01 = 0, apb10 = 0, apb11 = 0;
    float axx00 = 0, axx01 = 0, axx10 = 0, axx11 = 0;
#pragma unroll 4
    for (int d = 0; d < DD; d++) {
        float p0 = PbS[ty * 129 + d], p1 = PbS[(ty + 1) * 129 + d];
        float a0 = XnA[ty * 129 + d], a1 = XnA[(ty + 1) * 129 + d];
        float b0v = XnB[tx * 129 + d], b1v = XnB[(tx + 1) * 129 + d];
        apb00 += p0 * b0v; apb01 += p0 * b1v;
        apb10 += p1 * b0v; apb11 += p1 * b1v;
        axx00 += a0 * b0v; axx01 += a0 * b1v;
        axx10 += a1 * b0v; axx11 += a1 * b1v;
    }
    float dg0 = dgS[tx], dg1 = dgS[tx + 1];
    float a00 = fmaxf(0.5f * (apb00 + dg0), 0.f) + fmaxf(axx00, 0.f);
    float a01 = fmaxf(0.5f * (apb01 + dg1), 0.f) + fmaxf(axx01, 0.f);
    float a10 = fmaxf(0.5f * (apb10 + dg0), 0.f) + fmaxf(axx10, 0.f);
    float a11 = fmaxf(0.5f * (apb11 + dg1), 0.f) + fmaxf(axx11, 0.f);
    g_att[(b0 + ty) * BB + j0 + tx]         = a00;
    g_att[(b0 + ty) * BB + j0 + tx + 1]     = a01;
    g_att[(b0 + ty + 1) * BB + j0 + tx]     = a10;
    g_att[(b0 + ty + 1) * BB + j0 + tx + 1] = a11;

    atomicAdd(&rsum[ty], a00 + a01);
    atomicAdd(&rsum[ty + 1], a10 + a11);
    __syncthreads();
    if (tid < 32) atomicAdd(&g_rowsum[b0 + tid], rsum[tid]);
}

// ---------------------------------------------------------------------------
// K3 (fused): blocks [0,256): TWO xw rows each; blocks [256,256+PN_X): pnorm.
// ---------------------------------------------------------------------------
__global__ void __launch_bounds__(256) k_xw_pn(const float* __restrict__ proxies) {
    int bid = blockIdx.x;
    if (bid >= 256) { pnorm_group(proxies, PN_A + (bid - 256)); return; }

    __shared__ float ws[2][BB];
    __shared__ float4 part[8][2][32];
    __shared__ float sred[16];
    int tid = threadIdx.x;
    int b0 = bid * 2;
    int kp = tid >> 5, d4 = tid & 31;

    for (int i = tid; i < BB; i += 256) {
        float inv = 1.f / (g_rowsum[i] + ATT_EPS);
        ws[0][i] = g_att[(b0 + 0) * BB + i] * inv;
        ws[1][i] = g_att[(b0 + 1) * BB + i] * inv;
    }
    __syncthreads();

    const float4* Xn4 = (const float4*)g_Xn;
    float4 a0 = make_float4(0.f, 0.f, 0.f, 0.f);
    float4 a1 = make_float4(0.f, 0.f, 0.f, 0.f);
    int k0 = kp * 64;
#pragma unroll 4
    for (int kk = 0; kk < 64; kk++) {
        int k = k0 + kk;
        float4 x = Xn4[k * 32 + d4];
        float w0 = ws[0][k], w1 = ws[1][k];
        a0.x += w0 * x.x; a0.y += w0 * x.y; a0.z += w0 * x.z; a0.w += w0 * x.w;
        a1.x += w1 * x.x; a1.y += w1 * x.y; a1.z += w1 * x.z; a1.w += w1 * x.w;
    }
    part[kp][0][d4] = a0;
    part[kp][1][d4] = a1;
    __syncthreads();

    int r = tid >> 7, d = tid & 127;
    float s = 0.f;
    const float* pf = (const float*)part;
#pragma unroll
    for (int j = 0; j < 8; j++) s += pf[j * 256 + r * 128 + d];
    float x2 = g_Xn[(b0 + r) * DD + d] + s;

    float ssq = x2 * x2;
#pragma unroll
    for (int o = 16; o; o >>= 1) ssq += __shfl_xor_sync(0xffffffffu, ssq, o);
    if ((tid & 31) == 0) sred[tid >> 5] = ssq;
    __syncthreads();
    float tot = sred[r * 4] + sred[r * 4 + 1] + sred[r * 4 + 2] + sred[r * 4 + 3];
    float sc = 3.f / fmaxf(sqrtf(tot), 1e-12f);
    float xs = x2 * sc;
    g_Xs16[(b0 + r) * DD + d] = __float2bfloat16(xs);

    float dp = xs * g_Pb[(b0 + r) * DD + d];
#pragma unroll
    for (int o = 16; o; o >>= 1) dp += __shfl_xor_sync(0xffffffffu, dp, o);
    __syncthreads();
    if ((tid & 31) == 0) sred[tid >> 5] = dp;
    __syncthreads();
    if (d == 0) {
        float dt = sred[r * 4] + sred[r * 4 + 1] + sred[r * 4 + 2] + sred[r * 4 + 3];
        g_Dt[b0 + r] = fmaxf(18.f - 6.f * dt, 0.f);
    }
}

// ---------------------------------------------------------------------------
// K4 (big): Z[b] += sum_c exp(-relu(18 - 2*<Xs[b], pn[c]>))
// A persistent in registers (64 regs, loaded once); B tiles of 128 proxies,
// ring-3 cp.async buffers reusing the prologue A-staging smem; per n-pair
// (8 of them): B ldsm + mma -> immediate bit-trick exp2 epilogue (no MUFU).
// One wait_group + one __syncthreads per 128-proxy tile.
// ---------------------------------------------------------------------------
#define BROWB 272                       // bytes per padded B row (68 u32)
#define BBUFB (TCB * BROWB)             // 34816 bytes per B buffer
#define SMEM_BIG (BB * 68 * 4)          // A staging (139264) >= 3*BBUFB (104448)

__device__ __forceinline__ void cp_b(uint32_t s_b, int t, int buf, int tid) {
    if (t < NTB) {
        int r = tid >> 2;                    // row 0..127
        int jb = (tid & 3) * 4;              // chunk base 0,4,8,12
        int gr = t * TCB + r;
        int ok = gr < CC;
        const char* src = (const char*)(g_pn16 + (size_t)(ok ? gr : 0) * DD);
        uint32_t dst = s_b + buf * BBUFB + r * BROWB;
        int sz = ok ? 16 : 0;                // sz=0 -> zero-fill
#pragma unroll
        for (int jj = 0; jj < 4; jj++) {
            int j = jb + jj;
            asm volatile("cp.async.cg.shared.global [%0], [%1], 16, %2;"
                         :: "r"(dst + j * 16), "l"(src + j * 16), "r"(sz));
        }
    }
    asm volatile("cp.async.commit_group;");
}

__global__ void __launch_bounds__(512, 1) k_big() {
    extern __shared__ uint32_t smu[];
    uint32_t* As = smu;                      // prologue: 512 x 68 A staging
    const uint32_t s_as = s2u(As);
    const uint32_t s_b = s_as;               // B ring reuses the same smem

    const int tid = threadIdx.x;
    const int w = tid >> 5, lane = tid & 31, gid = lane >> 2, tig = lane & 3;
    const int grp = lane >> 3, lr = lane & 7;

    const int stride = gridDim.x;
    int t = blockIdx.x;

    // ---- prologue phase 1: stage A, load persistent A fragments ----
    {
        const uint32_t* Xg = (const uint32_t*)g_Xs16;
        for (int i = tid; i < BB * (DD / 2); i += 512)
            As[(i >> 6) * 68 + (i & 63)] = Xg[i];
    }
    __syncthreads();

    const uint32_t aRowBase = (uint32_t)(w * 32 + (grp & 1) * 8 + lr);
    const uint32_t aKadd = (uint32_t)((grp >> 1) * 4);
    uint32_t af[8][2][4];                    // persistent across all tiles
#pragma unroll
    for (int ks = 0; ks < 8; ks++) {
        uint32_t kb = ks * 8;
#pragma unroll
        for (int mf = 0; mf < 2; mf++)
            ldsm4(s_as + ((aRowBase + mf * 16) * 68 + kb + aKadd) * 4,
                  af[ks][mf]);
    }
    __syncthreads();   // all A reads done before B cp.async overwrites smem

    // ---- prologue phase 2: start B ring ----
    cp_b(s_b, t, 0, tid);
    cp_b(s_b, t + stride, 1, tid);

    float rs[2][2];
    rs[0][0] = rs[0][1] = rs[1][0] = rs[1][1] = 0.f;

    const uint32_t bRowBase = (uint32_t)((grp >> 1) * 8 + lr);
    const uint32_t bKadd = (uint32_t)((grp & 1) * 4);

    const float C2L = 2.8853900817779268f;   // 2*log2(e)
    const float SXL = 25.96851073600134f;    // 18*log2(e)

    int it = 0;
    for (; t < NTB; t += stride, it++) {
        asm volatile("cp.async.wait_group 1;");   // tile T(it) landed
        __syncthreads();                          // + iter it-1 reads done

        cp_b(s_b, t + 2 * stride, (it + 2) % 3, tid);

        const uint32_t s_bb = s_b + (it % 3) * BBUFB;

        // per n-pair (8 pairs of 16 proxies): B ldsm + mma, then epilogue
#pragma unroll
        for (int np = 0; np < 8; np++) {
            float acc[2][2][4];
#pragma unroll
            for (int mf = 0; mf < 2; mf++)
#pragma unroll
                for (int nn = 0; nn < 2; nn++) {
                    acc[mf][nn][0] = 0.f; acc[mf][nn][1] = 0.f;
                    acc[mf][nn][2] = 0.f; acc[mf][nn][3] = 0.f;
                }
#pragma unroll
            for (int ks = 0; ks < 8; ks++) {
                uint32_t kb = ks * 8;
                uint32_t r4[4];
                ldsm4(s_bb + ((bRowBase + np * 16) * 68 + kb + bKadd) * 4, r4);
#pragma unroll
                for (int mf = 0; mf < 2; mf++) {
                    mma_bf16(acc[mf][0], af[ks][mf][0], af[ks][mf][1],
                             af[ks][mf][2], af[ks][mf][3], r4[0], r4[1]);
                    mma_bf16(acc[mf][1], af[ks][mf][0], af[ks][mf][1],
                             af[ks][mf][2], af[ks][mf][3], r4[2], r4[3]);
                }
            }
            // epilogue: rs += 2^min(C2L*acc - SXL, 0)  (bit-trick, no MUFU)
#pragma unroll
            for (int mf = 0; mf < 2; mf++) {
#pragma unroll
                for (int nn = 0; nn < 2; nn++) {
                    float e0 = fminf(fmaf(C2L, acc[mf][nn][0], -SXL), 0.f);
                    float e1 = fminf(fmaf(C2L, acc[mf][nn][1], -SXL), 0.f);
                    float e2 = fminf(fmaf(C2L, acc[mf][nn][2], -SXL), 0.f);
                    float e3 = fminf(fmaf(C2L, acc[mf][nn][3], -SXL), 0.f);
                    rs[mf][0] += exp2_fast(e0) + exp2_fast(e1);
                    rs[mf][1] += exp2_fast(e2) + exp2_fast(e3);
                }
            }
        }
    }

    // flush: quad-reduce over tig, one atomicAdd per row
#pragma unroll
    for (int mf = 0; mf < 2; mf++) {
#pragma unroll
        for (int h = 0; h < 2; h++) {
            float v = rs[mf][h];
            v += __shfl_xor_sync(0xffffffffu, v, 1);
            v += __shfl_xor_sync(0xffffffffu, v, 2);
            if (tig == 0)
                atomicAdd(&g_Z[w * 32 + mf * 16 + h * 8 + gid], v);
        }
    }
}

// ---------------------------------------------------------------------------
// K5: out = mean_b( Dt[b] + log(Z[b]) )
// ---------------------------------------------------------------------------
__global__ void k_final(float* __restrict__ out) {
    __shared__ float sw[16];
    int tid = threadIdx.x;
    float v = g_Dt[tid] + logf(g_Z[tid]);
#pragma unroll
    for (int o = 16; o; o >>= 1) v += __shfl_xor_sync(0xffffffffu, v, o);
    if ((tid & 31) == 0) sw[tid >> 5] = v;
    __syncthreads();
    if (tid < 32) {
        float u = (tid < 16) ? sw[tid] : 0.f;
#pragma unroll
        for (int o = 8; o; o >>= 1) u += __shfl_xor_sync(0xffffffffu, u, o);
        if (tid == 0) out[0] = u / (float)BB;
    }
}

// ---------------------------------------------------------------------------
// launch
// ---------------------------------------------------------------------------
extern "C" void kernel_launch(void* const* d_in, const int* in_sizes, int n_in,
                              void* d_out, int out_size) {
    const float* X = (const float*)d_in[0];
    const int* T32 = (const int*)d_in[2];
    const float* proxies = (const float*)d_in[3];
    float* out = (float*)d_out;

    int sms = 0;
    cudaDeviceGetAttribute(&sms, cudaDevAttrMultiProcessorCount, 0);
    if (sms <= 0) sms = 148;
    cudaFuncSetAttribute(k_big, cudaFuncAttributeMaxDynamicSharedMemorySize, SMEM_BIG);
    cudaFuncSetAttribute(k_att_pn, cudaFuncAttributeMaxDynamicSharedMemorySize, SMEM_ATT);

    k_prep<<<BB, DD>>>(X, T32, proxies);
    k_att_pn<<<256 + PN_A, 256, SMEM_ATT>>>(proxies);
    k_xw_pn<<<256 + PN_X, 256>>>(proxies);
    k_big<<<sms, 512, SMEM_BIG>>>();
    k_final<<<1, BB>>>(out);
}

// round 15
// speedup vs baseline: 1.0889x; 1.0889x over previous
#include <cuda_runtime.h>
#include <cuda_bf16.h>
#include <cstdint>

// Problem constants
#define BB 512
#define DD 128
#define CC 100000
#define TCB 64                     // proxies per tile in k_big
#define NTB ((CC + TCB - 1) / TCB) // 1563 tiles (last zero-padded)
#define ATT_EPS 1e-5f
#define PN_A 1600                  // pnorm 32-row groups fused into att launch
#define PN_X (CC / 32 - PN_A)      // remaining groups fused into xw launch

// Scratch (device globals; no allocations allowed)
__device__ float g_Xn[BB * DD];
__device__ float g_Pb[BB * DD];
__device__ float g_diag[BB];
__device__ float g_att[BB * BB];
__device__ float g_rowsum[BB];
__device__ float g_Dt[BB];
__device__ float g_Z[BB];
__device__ int g_done;
__device__ __align__(16) __nv_bfloat16 g_Xs16[BB * DD];
__device__ __align__(16) __nv_bfloat16 g_pn16[CC * DD];   // 3 * l2norm(proxies), bf16

// ---------------------------------------------------------------------------
// helpers
// ---------------------------------------------------------------------------
__device__ __forceinline__ uint32_t s2u(const void* p) {
    uint32_t a;
    asm("{ .reg .u64 t; cvta.to.shared.u64 t, %1; cvt.u32.u64 %0, t; }"
        : "=r"(a) : "l"(p));
    return a;
}

__device__ __forceinline__ float bred128(float v, float* s4) {
#pragma unroll
    for (int o = 16; o; o >>= 1) v += __shfl_xor_sync(0xffffffffu, v, o);
    __syncthreads();
    if ((threadIdx.x & 31) == 0) s4[threadIdx.x >> 5] = v;
    __syncthreads();
    return s4[0] + s4[1] + s4[2] + s4[3];
}

__device__ __forceinline__ void mma_bf16(float* acc, uint32_t a0, uint32_t a1,
                                         uint32_t a2, uint32_t a3,
                                         uint32_t b0, uint32_t b1) {
    asm volatile(
        "mma.sync.aligned.m16n8k16.row.col.f32.bf16.bf16.f32 "
        "{%0,%1,%2,%3}, {%4,%5,%6,%7}, {%8,%9}, {%0,%1,%2,%3};\n"
        : "+f"(acc[0]), "+f"(acc[1]), "+f"(acc[2]), "+f"(acc[3])
        : "r"(a0), "r"(a1), "r"(a2), "r"(a3), "r"(b0), "r"(b1));
}

__device__ __forceinline__ void ldsm4(uint32_t addr, uint32_t* r) {
    asm volatile("ldmatrix.sync.aligned.m8n8.x4.shared.b16 {%0,%1,%2,%3}, [%4];"
                 : "=r"(r[0]), "=r"(r[1]), "=r"(r[2]), "=r"(r[3]) : "r"(addr));
}

__device__ __forceinline__ float ex2f(float x) {
    float r;
    asm("ex2.approx.ftz.f32 %0, %1;" : "=f"(r) : "f"(x));
    return r;
}

__device__ __forceinline__ uint32_t f2b2(float a, float b) {
    __nv_bfloat162 h = __floats2bfloat162_rn(a, b);
    return *(uint32_t*)&h;
}

// Robust class-id fetch (JAX x64-disabled materializes int32 for declared int64)
__device__ __forceinline__ int fetch_T(const int* T32, int b, int is64) {
    int t = is64 ? T32[2 * b] : T32[b];
    return min(max(t, 0), CC - 1);
}
__device__ __forceinline__ int detect_i64_block(const int* T32) {
    int ok = 1;
    for (int i = threadIdx.x; i < BB; i += blockDim.x)
        if (T32[2 * i + 1] != 0) ok = 0;
    return __syncthreads_and(ok);
}

// ---------------------------------------------------------------------------
// pnorm body: one 32-row group of g_pn16 = bf16(3*l2norm(proxy)), 256 threads,
// 8 threads per row. No smem, no barriers (safe to fuse into any launch).
// ---------------------------------------------------------------------------
__device__ __forceinline__ void pnorm_group(const float* __restrict__ proxies,
                                            int grp) {
    int tid = threadIdx.x;
    int r = grp * 32 + (tid >> 3);
    int sub = tid & 7;
    const float4* src = (const float4*)(proxies + (size_t)r * DD) + sub * 4;
    float4 q0 = src[0], q1 = src[1], q2 = src[2], q3 = src[3];
    float s = q0.x * q0.x + q0.y * q0.y + q0.z * q0.z + q0.w * q0.w
            + q1.x * q1.x + q1.y * q1.y + q1.z * q1.z + q1.w * q1.w
            + q2.x * q2.x + q2.y * q2.y + q2.z * q2.z + q2.w * q2.w
            + q3.x * q3.x + q3.y * q3.y + q3.z * q3.z + q3.w * q3.w;
    s += __shfl_xor_sync(0xffffffffu, s, 4);
    s += __shfl_xor_sync(0xffffffffu, s, 2);
    s += __shfl_xor_sync(0xffffffffu, s, 1);
    float sc = (s > 0.f) ? 3.f * rsqrtf(s) : 0.f;
    uint4 o0, o1;
    o0.x = f2b2(q0.x * sc, q0.y * sc); o0.y = f2b2(q0.z * sc, q0.w * sc);
    o0.z = f2b2(q1.x * sc, q1.y * sc); o0.w = f2b2(q1.z * sc, q1.w * sc);
    o1.x = f2b2(q2.x * sc, q2.y * sc); o1.y = f2b2(q2.z * sc, q2.w * sc);
    o1.z = f2b2(q3.x * sc, q3.y * sc); o1.w = f2b2(q3.z * sc, q3.w * sc);
    uint4* dst = (uint4*)(g_pn16 + (size_t)r * DD) + sub * 2;
    dst[0] = o0; dst[1] = o1;
}

// ---------------------------------------------------------------------------
// K1: Xn = l2norm(X); Pb = l2norm(proxies[T]); diag = <Pb,Xn>; zero Z/rowsum
//     + zero the k_big completion counter (graph-replay determinism)
// ---------------------------------------------------------------------------
__global__ void k_prep(const float* __restrict__ X,
                       const int* __restrict__ T32,
                       const float* __restrict__ proxies) {
    __shared__ float s4[4];
    int b = blockIdx.x, d = threadIdx.x;
    int is64 = detect_i64_block(T32);

    float x = X[b * DD + d];
    float s = bred128(x * x, s4);
    float xn = x / fmaxf(sqrtf(s), 1e-12f);
    g_Xn[b * DD + d] = xn;

    int t = fetch_T(T32, b, is64);
    float p = proxies[(size_t)t * DD + d];
    float s2 = bred128(p * p, s4);
    float pb = p / fmaxf(sqrtf(s2), 1e-12f);
    g_Pb[b * DD + d] = pb;

    float dg = bred128(pb * xn, s4);
    if (d == 0) g_diag[b] = dg;
    if (b < 4) { g_rowsum[b * DD + d] = 0.f; }
    if (d == 0) g_Z[b] = 0.f;
    if (b == 0 && d == 0) g_done = 0;
}

// ---------------------------------------------------------------------------
// K2 (fused): blocks [0,256): att tiles; blocks [256, 256+PN_A): pnorm groups.
// ---------------------------------------------------------------------------
#define SMEM_ATT ((3 * 32 * 129 + 32 + 32) * 4)
__global__ void __launch_bounds__(256) k_att_pn(const float* __restrict__ proxies) {
    int bid = blockIdx.x;
    if (bid >= 256) { pnorm_group(proxies, bid - 256); return; }

    extern __shared__ float smf[];
    float* PbS = smf;
    float* XnA = smf + 32 * 129;
    float* XnB = smf + 2 * 32 * 129;
    float* dgS = smf + 3 * 32 * 129;
    float* rsum = smf + 3 * 32 * 129 + 32;

    int tid = threadIdx.x;
    int b0 = (bid >> 4) * 32, j0 = (bid & 15) * 32;
    for (int i = tid; i < 32 * DD; i += 256) {
        int r = i >> 7, d = i & 127;
        PbS[r * 129 + d] = g_Pb[(b0 + r) * DD + d];
        XnA[r * 129 + d] = g_Xn[(b0 + r) * DD + d];
        XnB[r * 129 + d] = g_Xn[(j0 + r) * DD + d];
    }
    if (tid < 32) { dgS[tid] = g_diag[j0 + tid]; rsum[tid] = 0.f; }
    __syncthreads();

    int tx = (tid & 15) * 2, ty = (tid >> 4) * 2;
    float apb00 = 0, apb01 = 0, apb10 = 0, apb11 = 0;
    float axx00 = 0, axx01 = 0, axx10 = 0, axx11 = 0;
#pragma unroll 4
    for (int d = 0; d < DD; d++) {
        float p0 = PbS[ty * 129 + d], p1 = PbS[(ty + 1) * 129 + d];
        float a0 = XnA[ty * 129 + d], a1 = XnA[(ty + 1) * 129 + d];
        float b0v = XnB[tx * 129 + d], b1v = XnB[(tx + 1) * 129 + d];
        apb00 += p0 * b0v; apb01 += p0 * b1v;
        apb10 += p1 * b0v; apb11 += p1 * b1v;
        axx00 += a0 * b0v; axx01 += a0 * b1v;
        axx10 += a1 * b0v; axx11 += a1 * b1v;
    }
    float dg0 = dgS[tx], dg1 = dgS[tx + 1];
    float a00 = fmaxf(0.5f * (apb00 + dg0), 0.f) + fmaxf(axx00, 0.f);
    float a01 = fmaxf(0.5f * (apb01 + dg1), 0.f) + fmaxf(axx01, 0.f);
    float a10 = fmaxf(0.5f * (apb10 + dg0), 0.f) + fmaxf(axx10, 0.f);
    float a11 = fmaxf(0.5f * (apb11 + dg1), 0.f) + fmaxf(axx11, 0.f);
    g_att[(b0 + ty) * BB + j0 + tx]         = a00;
    g_att[(b0 + ty) * BB + j0 + tx + 1]     = a01;
    g_att[(b0 + ty + 1) * BB + j0 + tx]     = a10;
    g_att[(b0 + ty + 1) * BB + j0 + tx + 1] = a11;

    atomicAdd(&rsum[ty], a00 + a01);
    atomicAdd(&rsum[ty + 1], a10 + a11);
    __syncthreads();
    if (tid < 32) atomicAdd(&g_rowsum[b0 + tid], rsum[tid]);
}

// ---------------------------------------------------------------------------
// K3 (fused): blocks [0,256): TWO xw rows each; blocks [256,256+PN_X): pnorm.
// ---------------------------------------------------------------------------
__global__ void __launch_bounds__(256) k_xw_pn(const float* __restrict__ proxies) {
    int bid = blockIdx.x;
    if (bid >= 256) { pnorm_group(proxies, PN_A + (bid - 256)); return; }

    __shared__ float ws[2][BB];
    __shared__ float4 part[8][2][32];
    __shared__ float sred[16];
    int tid = threadIdx.x;
    int b0 = bid * 2;
    int kp = tid >> 5, d4 = tid & 31;

    for (int i = tid; i < BB; i += 256) {
        float inv = 1.f / (g_rowsum[i] + ATT_EPS);
        ws[0][i] = g_att[(b0 + 0) * BB + i] * inv;
        ws[1][i] = g_att[(b0 + 1) * BB + i] * inv;
    }
    __syncthreads();

    const float4* Xn4 = (const float4*)g_Xn;
    float4 a0 = make_float4(0.f, 0.f, 0.f, 0.f);
    float4 a1 = make_float4(0.f, 0.f, 0.f, 0.f);
    int k0 = kp * 64;
#pragma unroll 4
    for (int kk = 0; kk < 64; kk++) {
        int k = k0 + kk;
        float4 x = Xn4[k * 32 + d4];
        float w0 = ws[0][k], w1 = ws[1][k];
        a0.x += w0 * x.x; a0.y += w0 * x.y; a0.z += w0 * x.z; a0.w += w0 * x.w;
        a1.x += w1 * x.x; a1.y += w1 * x.y; a1.z += w1 * x.z; a1.w += w1 * x.w;
    }
    part[kp][0][d4] = a0;
    part[kp][1][d4] = a1;
    __syncthreads();

    int r = tid >> 7, d = tid & 127;
    float s = 0.f;
    const float* pf = (const float*)part;
#pragma unroll
    for (int j = 0; j < 8; j++) s += pf[j * 256 + r * 128 + d];
    float x2 = g_Xn[(b0 + r) * DD + d] + s;

    float ssq = x2 * x2;
#pragma unroll
    for (int o = 16; o; o >>= 1) ssq += __shfl_xor_sync(0xffffffffu, ssq, o);
    if ((tid & 31) == 0) sred[tid >> 5] = ssq;
    __syncthreads();
    float tot = sred[r * 4] + sred[r * 4 + 1] + sred[r * 4 + 2] + sred[r * 4 + 3];
    float sc = 3.f / fmaxf(sqrtf(tot), 1e-12f);
    float xs = x2 * sc;
    g_Xs16[(b0 + r) * DD + d] = __float2bfloat16(xs);

    float dp = xs * g_Pb[(b0 + r) * DD + d];
#pragma unroll
    for (int o = 16; o; o >>= 1) dp += __shfl_xor_sync(0xffffffffu, dp, o);
    __syncthreads();
    if ((tid & 31) == 0) sred[tid >> 5] = dp;
    __syncthreads();
    if (d == 0) {
        float dt = sred[r * 4] + sred[r * 4 + 1] + sred[r * 4 + 2] + sred[r * 4 + 3];
        g_Dt[b0 + r] = fmaxf(18.f - 6.f * dt, 0.f);
    }
}

// ---------------------------------------------------------------------------
// K4 (big): Z[b] += sum_c exp(-relu(18 - 2*<Xs[b], pn[c]>)), then the LAST
// CTA (completion counter) computes out = mean_b(Dt[b] + log(Z[b])).
// A persistent in registers (loaded once via prologue smem staging, then the
// B ring-3 reuses that smem). Per tile: 32 B-ldsm4 + 64 mma + ex2 epilogue.
// ---------------------------------------------------------------------------
#define BROWB 272                       // bytes per padded B row (68 u32)
#define BBUFB (TCB * BROWB)             // 17408 bytes per B buffer
#define SMEM_BIG (BB * 68 * 4)          // A staging (139264) >= 3*BBUFB

__device__ __forceinline__ void cp_b(uint32_t s_b, int t, int buf, int tid) {
    if (t < NTB) {
        int r = tid >> 3, j = tid & 7;       // row 0..63, chunks j and j+8
        int gr = t * TCB + r;
        int ok = gr < CC;
        const char* src = (const char*)(g_pn16 + (size_t)(ok ? gr : 0) * DD);
        uint32_t dst = s_b + buf * BBUFB + r * BROWB;
        int sz = ok ? 16 : 0;                // sz=0 -> zero-fill
        asm volatile("cp.async.cg.shared.global [%0], [%1], 16, %2;"
                     :: "r"(dst + j * 16), "l"(src + j * 16), "r"(sz));
        asm volatile("cp.async.cg.shared.global [%0], [%1], 16, %2;"
                     :: "r"(dst + (j + 8) * 16), "l"(src + (j + 8) * 16), "r"(sz));
    }
    asm volatile("cp.async.commit_group;");
}

__global__ void __launch_bounds__(512, 1) k_big(float* __restrict__ out) {
    extern __shared__ uint32_t smu[];
    uint32_t* As = smu;                      // prologue: 512 x 68 A staging
    const uint32_t s_as = s2u(As);
    const uint32_t s_b = s_as;               // B ring reuses the same smem

    const int tid = threadIdx.x;
    const int w = tid >> 5, lane = tid & 31, gid = lane >> 2, tig = lane & 3;
    const int grp = lane >> 3, lr = lane & 7;

    const int stride = gridDim.x;
    int t = blockIdx.x;

    // ---- prologue phase 1: stage A, load persistent A fragments ----
    {
        const uint32_t* Xg = (const uint32_t*)g_Xs16;
        for (int i = tid; i < BB * (DD / 2); i += 512)
            As[(i >> 6) * 68 + (i & 63)] = Xg[i];
    }
    __syncthreads();

    const uint32_t aRowBase = (uint32_t)(w * 32 + (grp & 1) * 8 + lr);
    const uint32_t aKadd = (uint32_t)((grp >> 1) * 4);
    uint32_t af[8][2][4];                    // persistent across all tiles
#pragma unroll
    for (int ks = 0; ks < 8; ks++) {
        uint32_t kb = ks * 8;
#pragma unroll
        for (int mf = 0; mf < 2; mf++)
            ldsm4(s_as + ((aRowBase + mf * 16) * 68 + kb + aKadd) * 4,
                  af[ks][mf]);
    }
    __syncthreads();   // all A reads done before B cp.async overwrites smem

    // ---- prologue phase 2: start B ring ----
    cp_b(s_b, t, 0, tid);
    cp_b(s_b, t + stride, 1, tid);

    float rs[2][2];
    rs[0][0] = rs[0][1] = rs[1][0] = rs[1][1] = 0.f;

    const uint32_t bRowBase = (uint32_t)((grp >> 1) * 8 + lr);
    const uint32_t bKadd = (uint32_t)((grp & 1) * 4);

    const float C2L = 2.8853900817779268f;   // 2*log2(e)
    const float SXL = 25.96851073600134f;    // 18*log2(e)

    int it = 0;
    for (; t < NTB; t += stride, it++) {
        asm volatile("cp.async.wait_group 1;");   // tile T(it) landed
        __syncthreads();                          // + iter it-1 reads done

        cp_b(s_b, t + 2 * stride, (it + 2) % 3, tid);

        const uint32_t s_bb = s_b + (it % 3) * BBUFB;

        // per n-pair: B ldsm + mma (A from registers), immediate epilogue
#pragma unroll
        for (int np = 0; np < 4; np++) {
            float acc[2][2][4];
#pragma unroll
            for (int mf = 0; mf < 2; mf++)
#pragma unroll
                for (int nn = 0; nn < 2; nn++) {
                    acc[mf][nn][0] = 0.f; acc[mf][nn][1] = 0.f;
                    acc[mf][nn][2] = 0.f; acc[mf][nn][3] = 0.f;
                }
#pragma unroll
            for (int ks = 0; ks < 8; ks++) {
                uint32_t kb = ks * 8;
                uint32_t r4[4];
                ldsm4(s_bb + ((bRowBase + np * 16) * 68 + kb + bKadd) * 4, r4);
#pragma unroll
                for (int mf = 0; mf < 2; mf++) {
                    mma_bf16(acc[mf][0], af[ks][mf][0], af[ks][mf][1],
                             af[ks][mf][2], af[ks][mf][3], r4[0], r4[1]);
                    mma_bf16(acc[mf][1], af[ks][mf][0], af[ks][mf][1],
                             af[ks][mf][2], af[ks][mf][3], r4[2], r4[3]);
                }
            }
#pragma unroll
            for (int mf = 0; mf < 2; mf++) {
#pragma unroll
                for (int nn = 0; nn < 2; nn++) {
                    float e0 = fminf(fmaf(C2L, acc[mf][nn][0], -SXL), 0.f);
                    float e1 = fminf(fmaf(C2L, acc[mf][nn][1], -SXL), 0.f);
                    float e2 = fminf(fmaf(C2L, acc[mf][nn][2], -SXL), 0.f);
                    float e3 = fminf(fmaf(C2L, acc[mf][nn][3], -SXL), 0.f);
                    rs[mf][0] += ex2f(e0) + ex2f(e1);
                    rs[mf][1] += ex2f(e2) + ex2f(e3);
                }
            }
        }
    }

    // flush: quad-reduce over tig, one atomicAdd per row
#pragma unroll
    for (int mf = 0; mf < 2; mf++) {
#pragma unroll
        for (int h = 0; h < 2; h++) {
            float v = rs[mf][h];
            v += __shfl_xor_sync(0xffffffffu, v, 1);
            v += __shfl_xor_sync(0xffffffffu, v, 2);
            if (tig == 0)
                atomicAdd(&g_Z[w * 32 + mf * 16 + h * 8 + gid], v);
        }
    }

    // ---- completion counter: last CTA computes the final loss ----
    __shared__ int s_last;
    __shared__ float sw[16];
    __threadfence();                    // release this CTA's Z atomics
    if (tid == 0) {
        int old = atomicAdd(&g_done, 1);
        s_last = (old == (int)gridDim.x - 1);
    }
    __syncthreads();
    if (s_last) {
        __threadfence();                // acquire all other CTAs' Z atomics
        float v = g_Dt[tid] + logf(g_Z[tid]);
#pragma unroll
        for (int o = 16; o; o >>= 1) v += __shfl_xor_sync(0xffffffffu, v, o);
        if (lane == 0) sw[w] = v;
        __syncthreads();
        if (tid < 32) {
            float u = (tid < 16) ? sw[tid] : 0.f;
#pragma unroll
            for (int o = 8; o; o >>= 1) u += __shfl_xor_sync(0xffffffffu, u, o);
            if (tid == 0) out[0] = u / (float)BB;
        }
    }
}

// ---------------------------------------------------------------------------
// launch
// ---------------------------------------------------------------------------
extern "C" void kernel_launch(void* const* d_in, const int* in_sizes, int n_in,
                              void* d_out, int out_size) {
    const float* X = (const float*)d_in[0];
    const int* T32 = (const int*)d_in[2];
    const float* proxies = (const float*)d_in[3];
    float* out = (float*)d_out;

    int sms = 0;
    cudaDeviceGetAttribute(&sms, cudaDevAttrMultiProcessorCount, 0);
    if (sms <= 0) sms = 148;
    cudaFuncSetAttribute(k_big, cudaFuncAttributeMaxDynamicSharedMemorySize, SMEM_BIG);
    cudaFuncSetAttribute(k_att_pn, cudaFuncAttributeMaxDynamicSharedMemorySize, SMEM_ATT);

    k_prep<<<BB, DD>>>(X, T32, proxies);
    k_att_pn<<<256 + PN_A, 256, SMEM_ATT>>>(proxies);
    k_xw_pn<<<256 + PN_X, 256>>>(proxies);
    k_big<<<sms, 512, SMEM_BIG>>>(out);
}

// round 16
// speedup vs baseline: 1.1034x; 1.0134x over previous
#include <cuda_runtime.h>
#include <cuda_bf16.h>
#include <cstdint>

// Problem constants
#define BB 512
#define DD 128
#define CC 100000
#define TCB 64                     // proxies per tile in k_big
#define NTB ((CC + TCB - 1) / TCB) // 1563 tiles (last zero-padded)
#define ATT_EPS 1e-5f
#define PN_A 1600                  // pnorm 32-row groups fused into att launch
#define PN_X (CC / 32 - PN_A)      // remaining groups fused into xw launch

// Scratch (device globals; no allocations allowed)
__device__ float g_Xn[BB * DD];
__device__ float g_Pb[BB * DD];
__device__ float g_diag[BB];
__device__ float g_att[BB * BB];
__device__ float g_rowsum[BB];
__device__ float g_Dt[BB];
__device__ float g_Z[BB];
__device__ int g_done;
__device__ __align__(16) __nv_bfloat16 g_Xs16[BB * DD];
__device__ __align__(16) __nv_bfloat16 g_pn16[CC * DD];   // 3 * l2norm(proxies), bf16

// ---------------------------------------------------------------------------
// helpers
// ---------------------------------------------------------------------------
__device__ __forceinline__ uint32_t s2u(const void* p) {
    uint32_t a;
    asm("{ .reg .u64 t; cvta.to.shared.u64 t, %1; cvt.u32.u64 %0, t; }"
        : "=r"(a) : "l"(p));
    return a;
}

__device__ __forceinline__ float bred128(float v, float* s4) {
#pragma unroll
    for (int o = 16; o; o >>= 1) v += __shfl_xor_sync(0xffffffffu, v, o);
    __syncthreads();
    if ((threadIdx.x & 31) == 0) s4[threadIdx.x >> 5] = v;
    __syncthreads();
    return s4[0] + s4[1] + s4[2] + s4[3];
}

__device__ __forceinline__ void mma_bf16(float* acc, uint32_t a0, uint32_t a1,
                                         uint32_t a2, uint32_t a3,
                                         uint32_t b0, uint32_t b1) {
    asm volatile(
        "mma.sync.aligned.m16n8k16.row.col.f32.bf16.bf16.f32 "
        "{%0,%1,%2,%3}, {%4,%5,%6,%7}, {%8,%9}, {%0,%1,%2,%3};\n"
        : "+f"(acc[0]), "+f"(acc[1]), "+f"(acc[2]), "+f"(acc[3])
        : "r"(a0), "r"(a1), "r"(a2), "r"(a3), "r"(b0), "r"(b1));
}

__device__ __forceinline__ void ldsm4(uint32_t addr, uint32_t* r) {
    asm volatile("ldmatrix.sync.aligned.m8n8.x4.shared.b16 {%0,%1,%2,%3}, [%4];"
                 : "=r"(r[0]), "=r"(r[1]), "=r"(r[2]), "=r"(r[3]) : "r"(addr));
}

__device__ __forceinline__ float ex2f(float x) {
    float r;
    asm("ex2.approx.ftz.f32 %0, %1;" : "=f"(r) : "f"(x));
    return r;
}

__device__ __forceinline__ uint32_t f2b2(float a, float b) {
    __nv_bfloat162 h = __floats2bfloat162_rn(a, b);
    return *(uint32_t*)&h;
}

// Robust class-id fetch (JAX x64-disabled materializes int32 for declared int64)
__device__ __forceinline__ int fetch_T(const int* T32, int b, int is64) {
    int t = is64 ? T32[2 * b] : T32[b];
    return min(max(t, 0), CC - 1);
}
__device__ __forceinline__ int detect_i64_block(const int* T32) {
    int ok = 1;
    for (int i = threadIdx.x; i < BB; i += blockDim.x)
        if (T32[2 * i + 1] != 0) ok = 0;
    return __syncthreads_and(ok);
}

// ---------------------------------------------------------------------------
// pnorm body: one 32-row group of g_pn16 = bf16(3*l2norm(proxy)), 256 threads,
// 8 threads per row. No smem, no barriers (safe to fuse into any launch).
// ---------------------------------------------------------------------------
__device__ __forceinline__ void pnorm_group(const float* __restrict__ proxies,
                                            int grp) {
    int tid = threadIdx.x;
    int r = grp * 32 + (tid >> 3);
    int sub = tid & 7;
    const float4* src = (const float4*)(proxies + (size_t)r * DD) + sub * 4;
    float4 q0 = src[0], q1 = src[1], q2 = src[2], q3 = src[3];
    float s = q0.x * q0.x + q0.y * q0.y + q0.z * q0.z + q0.w * q0.w
            + q1.x * q1.x + q1.y * q1.y + q1.z * q1.z + q1.w * q1.w
            + q2.x * q2.x + q2.y * q2.y + q2.z * q2.z + q2.w * q2.w
            + q3.x * q3.x + q3.y * q3.y + q3.z * q3.z + q3.w * q3.w;
    s += __shfl_xor_sync(0xffffffffu, s, 4);
    s += __shfl_xor_sync(0xffffffffu, s, 2);
    s += __shfl_xor_sync(0xffffffffu, s, 1);
    float sc = (s > 0.f) ? 3.f * rsqrtf(s) : 0.f;
    uint4 o0, o1;
    o0.x = f2b2(q0.x * sc, q0.y * sc); o0.y = f2b2(q0.z * sc, q0.w * sc);
    o0.z = f2b2(q1.x * sc, q1.y * sc); o0.w = f2b2(q1.z * sc, q1.w * sc);
    o1.x = f2b2(q2.x * sc, q2.y * sc); o1.y = f2b2(q2.z * sc, q2.w * sc);
    o1.z = f2b2(q3.x * sc, q3.y * sc); o1.w = f2b2(q3.z * sc, q3.w * sc);
    uint4* dst = (uint4*)(g_pn16 + (size_t)r * DD) + sub * 2;
    dst[0] = o0; dst[1] = o1;
}

// ---------------------------------------------------------------------------
// K1: Xn = l2norm(X); Pb = l2norm(proxies[T]); diag = <Pb,Xn>; zero Z/rowsum
//     + zero the k_big completion counter (graph-replay determinism)
// ---------------------------------------------------------------------------
__global__ void k_prep(const float* __restrict__ X,
                       const int* __restrict__ T32,
                       const float* __restrict__ proxies) {
    __shared__ float s4[4];
    int b = blockIdx.x, d = threadIdx.x;
    int is64 = detect_i64_block(T32);

    float x = X[b * DD + d];
    float s = bred128(x * x, s4);
    float xn = x / fmaxf(sqrtf(s), 1e-12f);
    g_Xn[b * DD + d] = xn;

    int t = fetch_T(T32, b, is64);
    float p = proxies[(size_t)t * DD + d];
    float s2 = bred128(p * p, s4);
    float pb = p / fmaxf(sqrtf(s2), 1e-12f);
    g_Pb[b * DD + d] = pb;

    float dg = bred128(pb * xn, s4);
    if (d == 0) g_diag[b] = dg;
    if (b < 4) { g_rowsum[b * DD + d] = 0.f; }
    if (d == 0) g_Z[b] = 0.f;
    if (b == 0 && d == 0) g_done = 0;
}

// ---------------------------------------------------------------------------
// K2 (fused): blocks [0,256): att tiles; blocks [256, 256+PN_A): pnorm groups.
// ---------------------------------------------------------------------------
#define SMEM_ATT ((3 * 32 * 129 + 32 + 32) * 4)
__global__ void __launch_bounds__(256) k_att_pn(const float* __restrict__ proxies) {
    int bid = blockIdx.x;
    if (bid >= 256) { pnorm_group(proxies, bid - 256); return; }

    extern __shared__ float smf[];
    float* PbS = smf;
    float* XnA = smf + 32 * 129;
    float* XnB = smf + 2 * 32 * 129;
    float* dgS = smf + 3 * 32 * 129;
    float* rsum = smf + 3 * 32 * 129 + 32;

    int tid = threadIdx.x;
    int b0 = (bid >> 4) * 32, j0 = (bid & 15) * 32;
    for (int i = tid; i < 32 * DD; i += 256) {
        int r = i >> 7, d = i & 127;
        PbS[r * 129 + d] = g_Pb[(b0 + r) * DD + d];
        XnA[r * 129 + d] = g_Xn[(b0 + r) * DD + d];
        XnB[r * 129 + d] = g_Xn[(j0 + r) * DD + d];
    }
    if (tid < 32) { dgS[tid] = g_diag[j0 + tid]; rsum[tid] = 0.f; }
    __syncthreads();

    int tx = (tid & 15) * 2, ty = (tid >> 4) * 2;
    float apb00 = 0, apb01 = 0, apb10 = 0, apb11 = 0;
    float axx00 = 0, axx01 = 0, axx10 = 0, axx11 = 0;
#pragma unroll 4
    for (int d = 0; d < DD; d++) {
        float p0 = PbS[ty * 129 + d], p1 = PbS[(ty + 1) * 129 + d];
        float a0 = XnA[ty * 129 + d], a1 = XnA[(ty + 1) * 129 + d];
        float b0v = XnB[tx * 129 + d], b1v = XnB[(tx + 1) * 129 + d];
        apb00 += p0 * b0v; apb01 += p0 * b1v;
        apb10 += p1 * b0v; apb11 += p1 * b1v;
        axx00 += a0 * b0v; axx01 += a0 * b1v;
        axx10 += a1 * b0v; axx11 += a1 * b1v;
    }
    float dg0 = dgS[tx], dg1 = dgS[tx + 1];
    float a00 = fmaxf(0.5f * (apb00 + dg0), 0.f) + fmaxf(axx00, 0.f);
    float a01 = fmaxf(0.5f * (apb01 + dg1), 0.f) + fmaxf(axx01, 0.f);
    float a10 = fmaxf(0.5f * (apb10 + dg0), 0.f) + fmaxf(axx10, 0.f);
    float a11 = fmaxf(0.5f * (apb11 + dg1), 0.f) + fmaxf(axx11, 0.f);
    g_att[(b0 + ty) * BB + j0 + tx]         = a00;
    g_att[(b0 + ty) * BB + j0 + tx + 1]     = a01;
    g_att[(b0 + ty + 1) * BB + j0 + tx]     = a10;
    g_att[(b0 + ty + 1) * BB + j0 + tx + 1] = a11;

    atomicAdd(&rsum[ty], a00 + a01);
    atomicAdd(&rsum[ty + 1], a10 + a11);
    __syncthreads();
    if (tid < 32) atomicAdd(&g_rowsum[b0 + tid], rsum[tid]);
}

// ---------------------------------------------------------------------------
// K3 (fused): blocks [0,256): TWO xw rows each; blocks [256,256+PN_X): pnorm.
// ---------------------------------------------------------------------------
__global__ void __launch_bounds__(256) k_xw_pn(const float* __restrict__ proxies) {
    int bid = blockIdx.x;
    if (bid >= 256) { pnorm_group(proxies, PN_A + (bid - 256)); return; }

    __shared__ float ws[2][BB];
    __shared__ float4 part[8][2][32];
    __shared__ float sred[16];
    int tid = threadIdx.x;
    int b0 = bid * 2;
    int kp = tid >> 5, d4 = tid & 31;

    for (int i = tid; i < BB; i += 256) {
        float inv = 1.f / (g_rowsum[i] + ATT_EPS);
        ws[0][i] = g_att[(b0 + 0) * BB + i] * inv;
        ws[1][i] = g_att[(b0 + 1) * BB + i] * inv;
    }
    __syncthreads();

    const float4* Xn4 = (const float4*)g_Xn;
    float4 a0 = make_float4(0.f, 0.f, 0.f, 0.f);
    float4 a1 = make_float4(0.f, 0.f, 0.f, 0.f);
    int k0 = kp * 64;
#pragma unroll 4
    for (int kk = 0; kk < 64; kk++) {
        int k = k0 + kk;
        float4 x = Xn4[k * 32 + d4];
        float w0 = ws[0][k], w1 = ws[1][k];
        a0.x += w0 * x.x; a0.y += w0 * x.y; a0.z += w0 * x.z; a0.w += w0 * x.w;
        a1.x += w1 * x.x; a1.y += w1 * x.y; a1.z += w1 * x.z; a1.w += w1 * x.w;
    }
    part[kp][0][d4] = a0;
    part[kp][1][d4] = a1;
    __syncthreads();

    int r = tid >> 7, d = tid & 127;
    float s = 0.f;
    const float* pf = (const float*)part;
#pragma unroll
    for (int j = 0; j < 8; j++) s += pf[j * 256 + r * 128 + d];
    float x2 = g_Xn[(b0 + r) * DD + d] + s;

    float ssq = x2 * x2;
#pragma unroll
    for (int o = 16; o; o >>= 1) ssq += __shfl_xor_sync(0xffffffffu, ssq, o);
    if ((tid & 31) == 0) sred[tid >> 5] = ssq;
    __syncthreads();
    float tot = sred[r * 4] + sred[r * 4 + 1] + sred[r * 4 + 2] + sred[r * 4 + 3];
    float sc = 3.f / fmaxf(sqrtf(tot), 1e-12f);
    float xs = x2 * sc;
    g_Xs16[(b0 + r) * DD + d] = __float2bfloat16(xs);

    float dp = xs * g_Pb[(b0 + r) * DD + d];
#pragma unroll
    for (int o = 16; o; o >>= 1) dp += __shfl_xor_sync(0xffffffffu, dp, o);
    __syncthreads();
    if ((tid & 31) == 0) sred[tid >> 5] = dp;
    __syncthreads();
    if (d == 0) {
        float dt = sred[r * 4] + sred[r * 4 + 1] + sred[r * 4 + 2] + sred[r * 4 + 3];
        g_Dt[b0 + r] = fmaxf(18.f - 6.f * dt, 0.f);
    }
}

// ---------------------------------------------------------------------------
// K4 (big): Z[b] += sum_c exp(-relu(18 - 2*<Xs[b], pn[c]>)), last CTA folds
// the final loss. 1024 threads (32 warps, 50% occ): warp w owns 16 rows
// [w*16, w*16+16) (mf=1, af = 32 persistent regs -> ~60 regs/thread, RF
// fits 1024 threads). Per tile per warp: 32 B-ldsm4 + 64 mma + epilogue.
// Ring-3 B buffers reuse the prologue A-staging smem.
// ---------------------------------------------------------------------------
#define BROWB 272                       // bytes per padded B row (68 u32)
#define BBUFB (TCB * BROWB)             // 17408 bytes per B buffer
#define SMEM_BIG (BB * 68 * 4)          // A staging (139264) >= 3*BBUFB

__device__ __forceinline__ void cp_b(uint32_t s_b, int t, int buf, int tid) {
    if (t < NTB) {
        int r = tid >> 4, j = tid & 15;      // row 0..63, chunk 0..15 (exact)
        int gr = t * TCB + r;
        int ok = gr < CC;
        const char* src = (const char*)(g_pn16 + (size_t)(ok ? gr : 0) * DD);
        uint32_t dst = s_b + buf * BBUFB + r * BROWB + j * 16;
        int sz = ok ? 16 : 0;                // sz=0 -> zero-fill
        asm volatile("cp.async.cg.shared.global [%0], [%1], 16, %2;"
                     :: "r"(dst), "l"(src + j * 16), "r"(sz));
    }
    asm volatile("cp.async.commit_group;");
}

__global__ void __launch_bounds__(1024, 1) k_big(float* __restrict__ out) {
    extern __shared__ uint32_t smu[];
    uint32_t* As = smu;                      // prologue: 512 x 68 A staging
    const uint32_t s_as = s2u(As);
    const uint32_t s_b = s_as;               // B ring reuses the same smem

    const int tid = threadIdx.x;
    const int w = tid >> 5, lane = tid & 31, gid = lane >> 2, tig = lane & 3;
    const int grp = lane >> 3, lr = lane & 7;

    const int stride = gridDim.x;
    int t = blockIdx.x;

    // ---- prologue phase 1: stage A, load persistent A fragments ----
    {
        const uint32_t* Xg = (const uint32_t*)g_Xs16;
        for (int i = tid; i < BB * (DD / 2); i += 1024)
            As[(i >> 6) * 68 + (i & 63)] = Xg[i];
    }
    __syncthreads();

    uint32_t af[8][4];                       // persistent across all tiles
    {
        const uint32_t aRowBase = (uint32_t)(w * 16 + (grp & 1) * 8 + lr);
        const uint32_t aKadd = (uint32_t)((grp >> 1) * 4);
#pragma unroll
        for (int ks = 0; ks < 8; ks++)
            ldsm4(s_as + (aRowBase * 68 + ks * 8 + aKadd) * 4, af[ks]);
    }
    __syncthreads();   // all A reads done before B cp.async overwrites smem

    // ---- prologue phase 2: start B ring ----
    cp_b(s_b, t, 0, tid);
    cp_b(s_b, t + stride, 1, tid);

    float rs0 = 0.f, rs1 = 0.f;              // rows w*16+gid, w*16+8+gid

    const uint32_t bAddrBase = ((uint32_t)((grp >> 1) * 8 + lr) * 68 +
                                (uint32_t)((grp & 1) * 4)) * 4;

    const float C2L = 2.8853900817779268f;   // 2*log2(e)
    const float SXL = 25.96851073600134f;    // 18*log2(e)

    int it = 0;
    for (; t < NTB; t += stride, it++) {
        asm volatile("cp.async.wait_group 1;");   // tile T(it) landed
        __syncthreads();                          // + iter it-1 reads done

        cp_b(s_b, t + 2 * stride, (it + 2) % 3, tid);

        const uint32_t s_bb = s_b + (it % 3) * BBUFB + bAddrBase;

        // per n-pair: B ldsm + mma (A from registers), immediate epilogue
#pragma unroll
        for (int np = 0; np < 4; np++) {
            float acc[2][4];
#pragma unroll
            for (int nn = 0; nn < 2; nn++) {
                acc[nn][0] = 0.f; acc[nn][1] = 0.f;
                acc[nn][2] = 0.f; acc[nn][3] = 0.f;
            }
#pragma unroll
            for (int ks = 0; ks < 8; ks++) {
                uint32_t r4[4];
                ldsm4(s_bb + (np * 16 * 68 + ks * 8) * 4, r4);
                mma_bf16(acc[0], af[ks][0], af[ks][1], af[ks][2], af[ks][3],
                         r4[0], r4[1]);
                mma_bf16(acc[1], af[ks][0], af[ks][1], af[ks][2], af[ks][3],
                         r4[2], r4[3]);
            }
#pragma unroll
            for (int nn = 0; nn < 2; nn++) {
                float e0 = fminf(fmaf(C2L, acc[nn][0], -SXL), 0.f);
                float e1 = fminf(fmaf(C2L, acc[nn][1], -SXL), 0.f);
                float e2 = fminf(fmaf(C2L, acc[nn][2], -SXL), 0.f);
                float e3 = fminf(fmaf(C2L, acc[nn][3], -SXL), 0.f);
                rs0 += ex2f(e0) + ex2f(e1);
                rs1 += ex2f(e2) + ex2f(e3);
            }
        }
    }

    // flush: quad-reduce over tig, one atomicAdd per row
    {
        float v0 = rs0, v1 = rs1;
        v0 += __shfl_xor_sync(0xffffffffu, v0, 1);
        v0 += __shfl_xor_sync(0xffffffffu, v0, 2);
        v1 += __shfl_xor_sync(0xffffffffu, v1, 1);
        v1 += __shfl_xor_sync(0xffffffffu, v1, 2);
        if (tig == 0) {
            atomicAdd(&g_Z[w * 16 + gid], v0);
            atomicAdd(&g_Z[w * 16 + 8 + gid], v1);
        }
    }

    // ---- completion counter: last CTA computes the final loss ----
    __shared__ int s_last;
    __shared__ float sw[16];
    __threadfence();                    // release this CTA's Z atomics
    if (tid == 0) {
        int old = atomicAdd(&g_done, 1);
        s_last = (old == (int)gridDim.x - 1);
    }
    __syncthreads();
    if (s_last) {
        __threadfence();                // acquire all other CTAs' Z atomics
        float v = (tid < BB) ? (g_Dt[tid] + logf(g_Z[tid])) : 0.f;
#pragma unroll
        for (int o = 16; o; o >>= 1) v += __shfl_xor_sync(0xffffffffu, v, o);
        if (lane == 0 && w < 16) sw[w] = v;
        __syncthreads();
        if (tid < 32) {
            float u = (tid < 16) ? sw[tid] : 0.f;
#pragma unroll
            for (int o = 8; o; o >>= 1) u += __shfl_xor_sync(0xffffffffu, u, o);
            if (tid == 0) out[0] = u / (float)BB;
        }
    }
}

// ---------------------------------------------------------------------------
// launch
// ---------------------------------------------------------------------------
extern "C" void kernel_launch(void* const* d_in, const int* in_sizes, int n_in,
                              void* d_out, int out_size) {
    const float* X = (const float*)d_in[0];
    const int* T32 = (const int*)d_in[2];
    const float* proxies = (const float*)d_in[3];
    float* out = (float*)d_out;

    int sms = 0;
    cudaDeviceGetAttribute(&sms, cudaDevAttrMultiProcessorCount, 0);
    if (sms <= 0) sms = 148;
    cudaFuncSetAttribute(k_big, cudaFuncAttributeMaxDynamicSharedMemorySize, SMEM_BIG);
    cudaFuncSetAttribute(k_att_pn, cudaFuncAttributeMaxDynamicSharedMemorySize, SMEM_ATT);

    k_prep<<<BB, DD>>>(X, T32, proxies);
    k_att_pn<<<256 + PN_A, 256, SMEM_ATT>>>(proxies);
    k_xw_pn<<<256 + PN_X, 256>>>(proxies);
    k_big<<<sms, 1024, SMEM_BIG>>>(out);
}